// round 4
// baseline (speedup 1.0000x reference)
#include <cuda_runtime.h>
#include <math.h>

// Problem constants
#define T_TOK 32768      // 8 * 4096 tokens
#define HDIM  1024
#define NEXP  64
#define TOPK  8
#define NB    8
#define SEQ   4096
#define TILE  64         // tokens per CTA
#define KC    256        // k-panel width (Eigen gebp-style accumulator restart)

// Per-(batch, expert) accumulators for aux loss + counts.
__device__ int   g_cnt [NB * NEXP];
__device__ float g_ssum[NB * NEXP];

__global__ void zero_kernel() {
    int i = threadIdx.x;
    if (i < NB * NEXP) { g_cnt[i] = 0; g_ssum[i] = 0.0f; }
}

// One CTA: 64 tokens x 64 experts. fp32 FMA GEMM, sequential-k within
// KC-panels with accumulator restart per panel (mimics Eigen gebp / the
// reference's rounding-error structure). Fused softmax (fp64 exp), top-8,
// renorm, histogram, score column-sums.
__global__ __launch_bounds__(256) void gate_kernel(
    const float* __restrict__ hs,   // [T_TOK, HDIM]
    const float* __restrict__ w,    // [NEXP, HDIM]
    float* __restrict__ out)        // flat f32: [idx | weights | aux | counts]
{
    __shared__ float a_s[TILE][33];        // token tile (padded)
    __shared__ float b_s[NEXP][33];        // weight tile
    __shared__ float s_p[TILE][NEXP + 1];  // logits -> probs
    __shared__ int   s_hist[NEXP];

    const int tid   = threadIdx.x;
    const int tBase = blockIdx.x * TILE;
    const int b     = blockIdx.x >> 6;     // 64 CTAs per batch

    if (tid < NEXP) s_hist[tid] = 0;

    float acc[4][4];   // current k-panel accumulator
    float tot[4][4];   // sum of completed panels
#pragma unroll
    for (int i = 0; i < 4; ++i)
#pragma unroll
        for (int j = 0; j < 4; ++j) { acc[i][j] = 0.0f; tot[i][j] = 0.0f; }

    const int trow = tid >> 4;     // 0..15 token group
    const int tcol = tid & 15;     // 0..15 expert group
    const int r0 = trow * 4;
    const int c0 = tcol * 4;

    for (int kk = 0; kk < HDIM; kk += 32) {
        for (int i = tid; i < TILE * 8; i += 256) {
            int row = i >> 3;
            int c4  = (i & 7) << 2;
            float4 v = *reinterpret_cast<const float4*>(
                &hs[(size_t)(tBase + row) * HDIM + kk + c4]);
            a_s[row][c4 + 0] = v.x; a_s[row][c4 + 1] = v.y;
            a_s[row][c4 + 2] = v.z; a_s[row][c4 + 3] = v.w;
            float4 u = *reinterpret_cast<const float4*>(
                &w[(size_t)row * HDIM + kk + c4]);
            b_s[row][c4 + 0] = u.x; b_s[row][c4 + 1] = u.y;
            b_s[row][c4 + 2] = u.z; b_s[row][c4 + 3] = u.w;
        }
        __syncthreads();

#pragma unroll
        for (int k = 0; k < 32; ++k) {
            float a0 = a_s[r0 + 0][k], a1 = a_s[r0 + 1][k];
            float a2 = a_s[r0 + 2][k], a3 = a_s[r0 + 3][k];
            float e0 = b_s[c0 + 0][k], e1 = b_s[c0 + 1][k];
            float e2 = b_s[c0 + 2][k], e3 = b_s[c0 + 3][k];
            acc[0][0] = fmaf(a0, e0, acc[0][0]); acc[0][1] = fmaf(a0, e1, acc[0][1]);
            acc[0][2] = fmaf(a0, e2, acc[0][2]); acc[0][3] = fmaf(a0, e3, acc[0][3]);
            acc[1][0] = fmaf(a1, e0, acc[1][0]); acc[1][1] = fmaf(a1, e1, acc[1][1]);
            acc[1][2] = fmaf(a1, e2, acc[1][2]); acc[1][3] = fmaf(a1, e3, acc[1][3]);
            acc[2][0] = fmaf(a2, e0, acc[2][0]); acc[2][1] = fmaf(a2, e1, acc[2][1]);
            acc[2][2] = fmaf(a2, e2, acc[2][2]); acc[2][3] = fmaf(a2, e3, acc[2][3]);
            acc[3][0] = fmaf(a3, e0, acc[3][0]); acc[3][1] = fmaf(a3, e1, acc[3][1]);
            acc[3][2] = fmaf(a3, e2, acc[3][2]); acc[3][3] = fmaf(a3, e3, acc[3][3]);
        }

        // End of a KC-panel: fold panel sum into total, restart panel acc.
        if (((kk + 32) & (KC - 1)) == 0) {
#pragma unroll
            for (int i = 0; i < 4; ++i)
#pragma unroll
                for (int j = 0; j < 4; ++j) {
                    tot[i][j] += acc[i][j];
                    acc[i][j] = 0.0f;
                }
        }
        __syncthreads();
    }

#pragma unroll
    for (int i = 0; i < 4; ++i)
#pragma unroll
        for (int j = 0; j < 4; ++j)
            s_p[r0 + i][c0 + j] = tot[i][j];
    __syncthreads();

    if (tid < TILE) {
        const int t = tid;
        // softmax over 64 logits; exp in fp64 -> correctly-rounded fp32 scores
        float m = -1e30f;
#pragma unroll 8
        for (int e = 0; e < NEXP; ++e) m = fmaxf(m, s_p[t][e]);
        float sum = 0.0f;
#pragma unroll 8
        for (int e = 0; e < NEXP; ++e) {
            float p = (float)exp((double)(s_p[t][e] - m));
            s_p[t][e] = p;
            sum += p;
        }
        float inv = (float)(1.0 / (double)sum);
#pragma unroll 8
        for (int e = 0; e < NEXP; ++e) s_p[t][e] *= inv;

        // top-8, descending, lowest index first on exact ties (lax.top_k)
        int   idx[TOPK];
        float wk [TOPK];
        float wsum = 0.0f;
#pragma unroll
        for (int s = 0; s < TOPK; ++s) {
            float best = -1.0f; int bi = 0;
            for (int e = 0; e < NEXP; ++e) {
                float v = s_p[t][e];
                if (v > best) { best = v; bi = e; }
            }
            idx[s] = bi; wk[s] = best; wsum += best;
            s_p[t][bi] = -1.0f;
        }
#pragma unroll
        for (int s = 0; s < TOPK; ++s) s_p[t][idx[s]] = wk[s];  // restore

        float inv2 = (float)(1.0 / ((double)wsum + 1e-20));
        size_t gt = (size_t)tBase + t;
#pragma unroll
        for (int s = 0; s < TOPK; ++s) {
            out[gt * TOPK + s] = (float)idx[s];
            out[(size_t)T_TOK * TOPK + gt * TOPK + s] = wk[s] * inv2;
            atomicAdd(&s_hist[idx[s]], 1);
        }
    }
    __syncthreads();

    if (tid < NEXP) {
        const int e = tid;
        float cs = 0.0f;
        for (int t2 = 0; t2 < TILE; ++t2) cs += s_p[t2][e];
        atomicAdd(&g_ssum[b * NEXP + e], cs);
        atomicAdd(&g_cnt [b * NEXP + e], s_hist[e]);
    }
}

// aux = ALPHA * mean_b sum_e [cnt(b,e) * NEXP/(SEQ*TOPK)] * [ssum(b,e)/SEQ]
__global__ void final_kernel(float* __restrict__ out) {
    __shared__ float red[NEXP];
    int e = threadIdx.x;          // 64 threads
    int c = 0; float partial = 0.0f;
#pragma unroll
    for (int b = 0; b < NB; ++b) {
        int cb = g_cnt[b * NEXP + e];
        c += cb;
        partial += (float)cb * g_ssum[b * NEXP + e];
    }
    out[(size_t)T_TOK * 2 * TOPK + 1 + e] = (float)c;  // expert_counts
    red[e] = partial;
    __syncthreads();
    if (e == 0) {
        float s = 0.0f;
        for (int i = 0; i < NEXP; ++i) s += red[i];
        float aux = 0.01f * ((float)NEXP / (float)(SEQ * TOPK))
                          * (1.0f / (float)SEQ) * (1.0f / (float)NB) * s;
        out[(size_t)T_TOK * 2 * TOPK] = aux;           // aux_loss
    }
}

extern "C" void kernel_launch(void* const* d_in, const int* in_sizes, int n_in,
                              void* d_out, int out_size) {
    const float* hs = (const float*)d_in[0];   // hidden_states [8,4096,1024] f32
    const float* w  = (const float*)d_in[1];   // weight [64,1024] f32
    float* out = (float*)d_out;

    zero_kernel <<<1, 512>>>();
    gate_kernel <<<T_TOK / TILE, 256>>>(hs, w, out);
    final_kernel<<<1, NEXP>>>(out);
}